// round 4
// baseline (speedup 1.0000x reference)
#include <cuda_runtime.h>
#include <math.h>

#define N_E   2048
#define FEAT  512
#define REST  8
#define HEAD  8
#define LEN   64
#define LR    512              // LEN*REST
#define HLR   4096             // HEAD*LR

// scratch (device globals: allocation-free rule)
__device__ float g_q[(size_t)HEAD * N_E * LR];     // 32 MB, layout [h][n][lr]
__device__ float g_k[(size_t)HEAD * N_E * LR];
__device__ float g_d[(size_t)HEAD * N_E * LR];
__device__ float g_s[(size_t)HEAD * N_E * N_E];    // 128 MB, scores/weights [h][n][m]
__device__ float g_inv[3 * N_E];                   // rsqrt of per-n squared norms (q,k,d)

// ============================================================
// Projection GEMM: C[hq, c] = sum_f W[hq,f] * x[n(c), f, r(c)]
//   c = n*8 + r  (N = 16384), M = 512 (hq), K = 512 (f)
//   output scattered to g_{q,k,d}[h][n][l*8+r]
// ============================================================
__global__ __launch_bounds__(256, 2)
void proj_kernel(const float* __restrict__ Wq, const float* __restrict__ Wk,
                 const float* __restrict__ Wd, const float* __restrict__ x)
{
    const float* W = (blockIdx.z == 0) ? Wq : (blockIdx.z == 1) ? Wk : Wd;
    float* OUT     = (blockIdx.z == 0) ? g_q : (blockIdx.z == 1) ? g_k : g_d;

    __shared__ float As[16][132];   // [k][hq_local]
    __shared__ float Bs[16][132];   // [k][c_local]

    const int tid  = threadIdx.x;
    const int row0 = blockIdx.y * 128;   // hq
    const int col0 = blockIdx.x * 128;   // c = (n,r)
    const int tr = tid >> 4, tc = tid & 15;

    float acc[8][8];
#pragma unroll
    for (int i = 0; i < 8; i++)
#pragma unroll
        for (int j = 0; j < 8; j++) acc[i][j] = 0.f;

    for (int k0 = 0; k0 < FEAT; k0 += 16) {
        // A tile: 128 rows (hq) x 16 k, transposed into As[k][m]
#pragma unroll
        for (int i = 0; i < 2; i++) {
            int l = tid + i * 256;            // 512 float4 slots
            int r = l >> 2, c4 = (l & 3) << 2;
            float4 v = *(const float4*)(W + (size_t)(row0 + r) * FEAT + k0 + c4);
            As[c4 + 0][r] = v.x; As[c4 + 1][r] = v.y;
            As[c4 + 2][r] = v.z; As[c4 + 3][r] = v.w;
        }
        // B tile: 16 k rows x 128 c cols; B[f][c] = x[c/8][f][c%8]
#pragma unroll
        for (int i = 0; i < 2; i++) {
            int l  = tid + i * 256;
            int kf = l >> 5, c4 = (l & 31) << 2;
            int c  = col0 + c4;
            const float* p = x + (size_t)(c >> 3) * (FEAT * REST) + (size_t)(k0 + kf) * REST + (c & 7);
            *(float4*)&Bs[kf][c4] = *(const float4*)p;
        }
        __syncthreads();
#pragma unroll
        for (int k = 0; k < 16; k++) {
            float a[8], b[8];
            *(float4*)(a)     = *(const float4*)&As[k][tr * 4];
            *(float4*)(a + 4) = *(const float4*)&As[k][tr * 4 + 64];
            *(float4*)(b)     = *(const float4*)&Bs[k][tc * 4];
            *(float4*)(b + 4) = *(const float4*)&Bs[k][tc * 4 + 64];
#pragma unroll
            for (int i = 0; i < 8; i++)
#pragma unroll
                for (int j = 0; j < 8; j++) acc[i][j] += a[i] * b[j];
        }
        __syncthreads();
    }

    // store: hq -> (h, l), c -> (n, r); 4 consecutive c share n (c%8 in {0,4})
#pragma unroll
    for (int i = 0; i < 8; i++) {
        int hq = row0 + tr * 4 + (i & 3) + ((i >> 2) << 6);
        int h = hq >> 6, ql = hq & 63;
#pragma unroll
        for (int j = 0; j < 8; j += 4) {
            int c = col0 + tc * 4 + ((j >> 2) << 6);
            int n = c >> 3, r = c & 7;
            float4 v = make_float4(acc[i][j], acc[i][j + 1], acc[i][j + 2], acc[i][j + 3]);
            *(float4*)&OUT[(size_t)(h * N_E + n) * LR + ql * REST + r] = v;
        }
    }
}

// ============================================================
// Per-n inverse norms: g_inv[w][n] = rsqrt( sum_{h,lr} P[h][n][lr]^2 )
// ============================================================
__global__ void norm_kernel()
{
    const int which = blockIdx.y, n = blockIdx.x, tid = threadIdx.x;
    const float* P = (which == 0) ? g_q : (which == 1) ? g_k : g_d;
    float s = 0.f;
    for (int i = tid; i < 1024; i += 256) {          // 1024 float4 = 4096 floats
        int h = i >> 7, off = (i & 127) << 2;
        float4 v = *(const float4*)&P[(size_t)(h * N_E + n) * LR + off];
        s += v.x * v.x + v.y * v.y + v.z * v.z + v.w * v.w;
    }
#pragma unroll
    for (int o = 16; o; o >>= 1) s += __shfl_xor_sync(0xffffffffu, s, o);
    __shared__ float ws[8];
    if ((tid & 31) == 0) ws[tid >> 5] = s;
    __syncthreads();
    if (tid == 0) {
        float t = 0.f;
#pragma unroll
        for (int w = 0; w < 8; w++) t += ws[w];
        g_inv[which * N_E + n] = rsqrtf(t);
    }
}

// ============================================================
// Scores GEMM (NT): S[h][n][m] = inv_q[n]*inv_k[m] * sum_lr q[h][n][lr]*k[h][m][lr]
// ============================================================
__global__ __launch_bounds__(256, 2)
void scores_kernel()
{
    const int h = blockIdx.z;
    const float* A = g_q + (size_t)h * N_E * LR;   // [n][lr]
    const float* B = g_k + (size_t)h * N_E * LR;   // [m][lr]
    float* C = g_s + (size_t)h * N_E * N_E;

    __shared__ float As[16][132];
    __shared__ float Bs[16][132];

    const int tid = threadIdx.x;
    const int row0 = blockIdx.y * 128;   // n
    const int col0 = blockIdx.x * 128;   // m
    const int tr = tid >> 4, tc = tid & 15;

    float acc[8][8];
#pragma unroll
    for (int i = 0; i < 8; i++)
#pragma unroll
        for (int j = 0; j < 8; j++) acc[i][j] = 0.f;

    for (int k0 = 0; k0 < LR; k0 += 16) {
#pragma unroll
        for (int i = 0; i < 2; i++) {
            int l = tid + i * 256;
            int r = l >> 2, c4 = (l & 3) << 2;
            float4 va = *(const float4*)(A + (size_t)(row0 + r) * LR + k0 + c4);
            As[c4 + 0][r] = va.x; As[c4 + 1][r] = va.y;
            As[c4 + 2][r] = va.z; As[c4 + 3][r] = va.w;
            float4 vb = *(const float4*)(B + (size_t)(col0 + r) * LR + k0 + c4);
            Bs[c4 + 0][r] = vb.x; Bs[c4 + 1][r] = vb.y;
            Bs[c4 + 2][r] = vb.z; Bs[c4 + 3][r] = vb.w;
        }
        __syncthreads();
#pragma unroll
        for (int k = 0; k < 16; k++) {
            float a[8], b[8];
            *(float4*)(a)     = *(const float4*)&As[k][tr * 4];
            *(float4*)(a + 4) = *(const float4*)&As[k][tr * 4 + 64];
            *(float4*)(b)     = *(const float4*)&Bs[k][tc * 4];
            *(float4*)(b + 4) = *(const float4*)&Bs[k][tc * 4 + 64];
#pragma unroll
            for (int i = 0; i < 8; i++)
#pragma unroll
                for (int j = 0; j < 8; j++) acc[i][j] += a[i] * b[j];
        }
        __syncthreads();
    }

#pragma unroll
    for (int i = 0; i < 8; i++) {
        int rn = row0 + tr * 4 + (i & 3) + ((i >> 2) << 6);
        float iq = g_inv[rn];
#pragma unroll
        for (int j = 0; j < 8; j += 4) {
            int cm = col0 + tc * 4 + ((j >> 2) << 6);
            float4 v;
            v.x = acc[i][j + 0] * iq * g_inv[N_E + cm + 0];
            v.y = acc[i][j + 1] * iq * g_inv[N_E + cm + 1];
            v.z = acc[i][j + 2] * iq * g_inv[N_E + cm + 2];
            v.w = acc[i][j + 3] * iq * g_inv[N_E + cm + 3];
            *(float4*)&C[(size_t)rn * N_E + cm] = v;
        }
    }
}

// ============================================================
// Softmax over m (row length 2048), folding inv_d[m] into weights
// ============================================================
__global__ void softmax_kernel()
{
    const int row = blockIdx.x, tid = threadIdx.x;
    float* S = g_s + (size_t)row * N_E;

    float4 v0 = *(float4*)&S[tid * 4];
    float4 v1 = *(float4*)&S[1024 + tid * 4];

    float mx = fmaxf(fmaxf(fmaxf(v0.x, v0.y), fmaxf(v0.z, v0.w)),
                     fmaxf(fmaxf(v1.x, v1.y), fmaxf(v1.z, v1.w)));
#pragma unroll
    for (int o = 16; o; o >>= 1) mx = fmaxf(mx, __shfl_xor_sync(0xffffffffu, mx, o));
    __shared__ float sm_max[8];
    __shared__ float sm_sum[8];
    if ((tid & 31) == 0) sm_max[tid >> 5] = mx;
    __syncthreads();
    mx = sm_max[0];
#pragma unroll
    for (int w = 1; w < 8; w++) mx = fmaxf(mx, sm_max[w]);

    float4 e0, e1;
    e0.x = expf(v0.x - mx); e0.y = expf(v0.y - mx);
    e0.z = expf(v0.z - mx); e0.w = expf(v0.w - mx);
    e1.x = expf(v1.x - mx); e1.y = expf(v1.y - mx);
    e1.z = expf(v1.z - mx); e1.w = expf(v1.w - mx);

    float s = e0.x + e0.y + e0.z + e0.w + e1.x + e1.y + e1.z + e1.w;
#pragma unroll
    for (int o = 16; o; o >>= 1) s += __shfl_xor_sync(0xffffffffu, s, o);
    if ((tid & 31) == 0) sm_sum[tid >> 5] = s;
    __syncthreads();
    s = 0.f;
#pragma unroll
    for (int w = 0; w < 8; w++) s += sm_sum[w];
    float inv = 1.f / s;

    float4 d0 = *(const float4*)&g_inv[2 * N_E + tid * 4];
    float4 d1 = *(const float4*)&g_inv[2 * N_E + 1024 + tid * 4];
    e0.x *= inv * d0.x; e0.y *= inv * d0.y; e0.z *= inv * d0.z; e0.w *= inv * d0.w;
    e1.x *= inv * d1.x; e1.y *= inv * d1.y; e1.z *= inv * d1.z; e1.w *= inv * d1.w;
    *(float4*)&S[tid * 4] = e0;
    *(float4*)&S[1024 + tid * 4] = e1;
}

// ============================================================
// Combine GEMM (NN): out[n][h*512+lr] = sum_m S[h][n][m] * d[h][m][lr]
// ============================================================
__global__ __launch_bounds__(256, 2)
void combine_kernel(float* __restrict__ out)
{
    const int h = blockIdx.z;
    const float* A = g_s + (size_t)h * N_E * N_E;   // [n][m]
    const float* B = g_d + (size_t)h * N_E * LR;    // [m][lr]

    __shared__ float As[16][132];
    __shared__ float Bs[16][132];

    const int tid = threadIdx.x;
    const int row0 = blockIdx.y * 128;   // n
    const int col0 = blockIdx.x * 128;   // lr (512 total -> gridDim.x = 4)
    const int tr = tid >> 4, tc = tid & 15;

    float acc[8][8];
#pragma unroll
    for (int i = 0; i < 8; i++)
#pragma unroll
        for (int j = 0; j < 8; j++) acc[i][j] = 0.f;

    for (int k0 = 0; k0 < N_E; k0 += 16) {
        // A: 128 rows x 16 k, transposed
#pragma unroll
        for (int i = 0; i < 2; i++) {
            int l = tid + i * 256;
            int r = l >> 2, c4 = (l & 3) << 2;
            float4 v = *(const float4*)(A + (size_t)(row0 + r) * N_E + k0 + c4);
            As[c4 + 0][r] = v.x; As[c4 + 1][r] = v.y;
            As[c4 + 2][r] = v.z; As[c4 + 3][r] = v.w;
        }
        // B: 16 k rows x 128 cols, natural
#pragma unroll
        for (int i = 0; i < 2; i++) {
            int l  = tid + i * 256;
            int kf = l >> 5, c4 = (l & 31) << 2;
            *(float4*)&Bs[kf][c4] = *(const float4*)(B + (size_t)(k0 + kf) * LR + col0 + c4);
        }
        __syncthreads();
#pragma unroll
        for (int k = 0; k < 16; k++) {
            float a[8], b[8];
            *(float4*)(a)     = *(const float4*)&As[k][tr * 4];
            *(float4*)(a + 4) = *(const float4*)&As[k][tr * 4 + 64];
            *(float4*)(b)     = *(const float4*)&Bs[k][tc * 4];
            *(float4*)(b + 4) = *(const float4*)&Bs[k][tc * 4 + 64];
#pragma unroll
            for (int i = 0; i < 8; i++)
#pragma unroll
                for (int j = 0; j < 8; j++) acc[i][j] += a[i] * b[j];
        }
        __syncthreads();
    }

#pragma unroll
    for (int i = 0; i < 8; i++) {
        int rn = row0 + tr * 4 + (i & 3) + ((i >> 2) << 6);
#pragma unroll
        for (int j = 0; j < 8; j += 4) {
            int c = col0 + tc * 4 + ((j >> 2) << 6);
            float4 v = make_float4(acc[i][j], acc[i][j + 1], acc[i][j + 2], acc[i][j + 3]);
            *(float4*)&out[(size_t)rn * HLR + h * LR + c] = v;
        }
    }
}

// ============================================================
extern "C" void kernel_launch(void* const* d_in, const int* in_sizes, int n_in,
                              void* d_out, int out_size)
{
    const float* x  = (const float*)d_in[0];
    const float* Wq = (const float*)d_in[1];
    const float* Wk = (const float*)d_in[2];
    const float* Wd = (const float*)d_in[3];
    float* out = (float*)d_out;

    proj_kernel<<<dim3(128, 4, 3), 256>>>(Wq, Wk, Wd, x);
    norm_kernel<<<dim3(N_E, 3), 256>>>();
    scores_kernel<<<dim3(16, 16, HEAD), 256>>>();
    softmax_kernel<<<HEAD * N_E, 256>>>();
    combine_kernel<<<dim3(4, 16, HEAD), 256>>>(out);
}

// round 5
// speedup vs baseline: 1.6165x; 1.6165x over previous
#include <cuda_runtime.h>
#include <math.h>

#define N_E   2048
#define FEAT  512
#define REST  8
#define HEAD  8
#define LEN   64
#define LR    512              // LEN*REST
#define HLR   4096             // HEAD*LR

// scratch (device globals: allocation-free rule)
__device__ float g_q[(size_t)HEAD * N_E * LR];     // 32 MB, layout [h][n][lr]
__device__ float g_k[(size_t)HEAD * N_E * LR];
__device__ float g_d[(size_t)HEAD * N_E * LR];
__device__ float g_s[(size_t)HEAD * N_E * N_E];    // 128 MB, scores/weights [h][n][m]
__device__ float g_inv[3 * N_E];                   // rsqrt of per-n squared norms (q,k,d)

// ============================================================
// Projection GEMM: C[hq, c] = sum_f W[hq,f] * x[n(c), f, r(c)]
//   c = n*8 + r  (N = 16384), M = 512 (hq), K = 512 (f)
//   output scattered to g_{q,k,d}[h][n][l*8+r]
// ============================================================
__global__ __launch_bounds__(256, 2)
void proj_kernel(const float* __restrict__ Wq, const float* __restrict__ Wk,
                 const float* __restrict__ Wd, const float* __restrict__ x)
{
    const float* W = (blockIdx.z == 0) ? Wq : (blockIdx.z == 1) ? Wk : Wd;
    float* OUT     = (blockIdx.z == 0) ? g_q : (blockIdx.z == 1) ? g_k : g_d;

    __shared__ float As[16][132];   // [k][hq_local]
    __shared__ float Bs[16][132];   // [k][c_local]

    const int tid  = threadIdx.x;
    const int row0 = blockIdx.y * 128;   // hq
    const int col0 = blockIdx.x * 128;   // c = (n,r)
    const int tr = tid >> 4, tc = tid & 15;

    float acc[8][8];
#pragma unroll
    for (int i = 0; i < 8; i++)
#pragma unroll
        for (int j = 0; j < 8; j++) acc[i][j] = 0.f;

    for (int k0 = 0; k0 < FEAT; k0 += 16) {
        // A tile: 128 rows (hq) x 16 k, transposed into As[k][m]
#pragma unroll
        for (int i = 0; i < 2; i++) {
            int l = tid + i * 256;            // 512 float4 slots
            int r = l >> 2, c4 = (l & 3) << 2;
            float4 v = *(const float4*)(W + (size_t)(row0 + r) * FEAT + k0 + c4);
            As[c4 + 0][r] = v.x; As[c4 + 1][r] = v.y;
            As[c4 + 2][r] = v.z; As[c4 + 3][r] = v.w;
        }
        // B tile: 16 k rows x 128 c cols; B[f][c] = x[c/8][f][c%8]
#pragma unroll
        for (int i = 0; i < 2; i++) {
            int l  = tid + i * 256;
            int kf = l >> 5, c4 = (l & 31) << 2;
            int c  = col0 + c4;
            const float* p = x + (size_t)(c >> 3) * (FEAT * REST) + (size_t)(k0 + kf) * REST + (c & 7);
            *(float4*)&Bs[kf][c4] = *(const float4*)p;
        }
        __syncthreads();
#pragma unroll
        for (int k = 0; k < 16; k++) {
            float a[8], b[8];
            *(float4*)(a)     = *(const float4*)&As[k][tr * 4];
            *(float4*)(a + 4) = *(const float4*)&As[k][tr * 4 + 64];
            *(float4*)(b)     = *(const float4*)&Bs[k][tc * 4];
            *(float4*)(b + 4) = *(const float4*)&Bs[k][tc * 4 + 64];
#pragma unroll
            for (int i = 0; i < 8; i++)
#pragma unroll
                for (int j = 0; j < 8; j++) acc[i][j] += a[i] * b[j];
        }
        __syncthreads();
    }

    // store: hq -> (h, l), c -> (n, r); 4 consecutive c share n (c%8 in {0,4})
#pragma unroll
    for (int i = 0; i < 8; i++) {
        int hq = row0 + tr * 4 + (i & 3) + ((i >> 2) << 6);
        int h = hq >> 6, ql = hq & 63;
#pragma unroll
        for (int j = 0; j < 8; j += 4) {
            int c = col0 + tc * 4 + ((j >> 2) << 6);
            int n = c >> 3, r = c & 7;
            float4 v = make_float4(acc[i][j], acc[i][j + 1], acc[i][j + 2], acc[i][j + 3]);
            *(float4*)&OUT[(size_t)(h * N_E + n) * LR + ql * REST + r] = v;
        }
    }
}

// ============================================================
// Per-n inverse norms: g_inv[w][n] = rsqrt( sum_{h,lr} P[h][n][lr]^2 )
// ============================================================
__global__ void norm_kernel()
{
    const int which = blockIdx.y, n = blockIdx.x, tid = threadIdx.x;
    const float* P = (which == 0) ? g_q : (which == 1) ? g_k : g_d;
    float s = 0.f;
    for (int i = tid; i < 1024; i += 256) {          // 1024 float4 = 4096 floats
        int h = i >> 7, off = (i & 127) << 2;
        float4 v = *(const float4*)&P[(size_t)(h * N_E + n) * LR + off];
        s += v.x * v.x + v.y * v.y + v.z * v.z + v.w * v.w;
    }
#pragma unroll
    for (int o = 16; o; o >>= 1) s += __shfl_xor_sync(0xffffffffu, s, o);
    __shared__ float ws[8];
    if ((tid & 31) == 0) ws[tid >> 5] = s;
    __syncthreads();
    if (tid == 0) {
        float t = 0.f;
#pragma unroll
        for (int w = 0; w < 8; w++) t += ws[w];
        g_inv[which * N_E + n] = rsqrtf(t);
    }
}

// ============================================================
// Scores GEMM (NT): S[h][n][m] = inv_q[n]*inv_k[m] * sum_lr q[h][n][lr]*k[h][m][lr]
// ============================================================
__global__ __launch_bounds__(256, 2)
void scores_kernel()
{
    const int h = blockIdx.z;
    const float* A = g_q + (size_t)h * N_E * LR;   // [n][lr]
    const float* B = g_k + (size_t)h * N_E * LR;   // [m][lr]
    float* C = g_s + (size_t)h * N_E * N_E;

    __shared__ float As[16][132];
    __shared__ float Bs[16][132];

    const int tid = threadIdx.x;
    const int row0 = blockIdx.y * 128;   // n
    const int col0 = blockIdx.x * 128;   // m
    const int tr = tid >> 4, tc = tid & 15;

    float acc[8][8];
#pragma unroll
    for (int i = 0; i < 8; i++)
#pragma unroll
        for (int j = 0; j < 8; j++) acc[i][j] = 0.f;

    for (int k0 = 0; k0 < LR; k0 += 16) {
#pragma unroll
        for (int i = 0; i < 2; i++) {
            int l = tid + i * 256;
            int r = l >> 2, c4 = (l & 3) << 2;
            float4 va = *(const float4*)(A + (size_t)(row0 + r) * LR + k0 + c4);
            As[c4 + 0][r] = va.x; As[c4 + 1][r] = va.y;
            As[c4 + 2][r] = va.z; As[c4 + 3][r] = va.w;
            float4 vb = *(const float4*)(B + (size_t)(col0 + r) * LR + k0 + c4);
            Bs[c4 + 0][r] = vb.x; Bs[c4 + 1][r] = vb.y;
            Bs[c4 + 2][r] = vb.z; Bs[c4 + 3][r] = vb.w;
        }
        __syncthreads();
#pragma unroll
        for (int k = 0; k < 16; k++) {
            float a[8], b[8];
            *(float4*)(a)     = *(const float4*)&As[k][tr * 4];
            *(float4*)(a + 4) = *(const float4*)&As[k][tr * 4 + 64];
            *(float4*)(b)     = *(const float4*)&Bs[k][tc * 4];
            *(float4*)(b + 4) = *(const float4*)&Bs[k][tc * 4 + 64];
#pragma unroll
            for (int i = 0; i < 8; i++)
#pragma unroll
                for (int j = 0; j < 8; j++) acc[i][j] += a[i] * b[j];
        }
        __syncthreads();
    }

#pragma unroll
    for (int i = 0; i < 8; i++) {
        int rn = row0 + tr * 4 + (i & 3) + ((i >> 2) << 6);
        float iq = g_inv[rn];
#pragma unroll
        for (int j = 0; j < 8; j += 4) {
            int cm = col0 + tc * 4 + ((j >> 2) << 6);
            float4 v;
            v.x = acc[i][j + 0] * iq * g_inv[N_E + cm + 0];
            v.y = acc[i][j + 1] * iq * g_inv[N_E + cm + 1];
            v.z = acc[i][j + 2] * iq * g_inv[N_E + cm + 2];
            v.w = acc[i][j + 3] * iq * g_inv[N_E + cm + 3];
            *(float4*)&C[(size_t)rn * N_E + cm] = v;
        }
    }
}

// ============================================================
// Softmax over m (row length 2048), folding inv_d[m] into weights
// ============================================================
__global__ void softmax_kernel()
{
    const int row = blockIdx.x, tid = threadIdx.x;
    float* S = g_s + (size_t)row * N_E;

    float4 v0 = *(float4*)&S[tid * 4];
    float4 v1 = *(float4*)&S[1024 + tid * 4];

    float mx = fmaxf(fmaxf(fmaxf(v0.x, v0.y), fmaxf(v0.z, v0.w)),
                     fmaxf(fmaxf(v1.x, v1.y), fmaxf(v1.z, v1.w)));
#pragma unroll
    for (int o = 16; o; o >>= 1) mx = fmaxf(mx, __shfl_xor_sync(0xffffffffu, mx, o));
    __shared__ float sm_max[8];
    __shared__ float sm_sum[8];
    if ((tid & 31) == 0) sm_max[tid >> 5] = mx;
    __syncthreads();
    mx = sm_max[0];
#pragma unroll
    for (int w = 1; w < 8; w++) mx = fmaxf(mx, sm_max[w]);

    float4 e0, e1;
    e0.x = expf(v0.x - mx); e0.y = expf(v0.y - mx);
    e0.z = expf(v0.z - mx); e0.w = expf(v0.w - mx);
    e1.x = expf(v1.x - mx); e1.y = expf(v1.y - mx);
    e1.z = expf(v1.z - mx); e1.w = expf(v1.w - mx);

    float s = e0.x + e0.y + e0.z + e0.w + e1.x + e1.y + e1.z + e1.w;
#pragma unroll
    for (int o = 16; o; o >>= 1) s += __shfl_xor_sync(0xffffffffu, s, o);
    if ((tid & 31) == 0) sm_sum[tid >> 5] = s;
    __syncthreads();
    s = 0.f;
#pragma unroll
    for (int w = 0; w < 8; w++) s += sm_sum[w];
    float inv = 1.f / s;

    float4 d0 = *(const float4*)&g_inv[2 * N_E + tid * 4];
    float4 d1 = *(const float4*)&g_inv[2 * N_E + 1024 + tid * 4];
    e0.x *= inv * d0.x; e0.y *= inv * d0.y; e0.z *= inv * d0.z; e0.w *= inv * d0.w;
    e1.x *= inv * d1.x; e1.y *= inv * d1.y; e1.z *= inv * d1.z; e1.w *= inv * d1.w;
    *(float4*)&S[tid * 4] = e0;
    *(float4*)&S[1024 + tid * 4] = e1;
}

// ============================================================
// Combine GEMM (NN): out[n][h*512+lr] = sum_m S[h][n][m] * d[h][m][lr]
// ============================================================
__global__ __launch_bounds__(256, 2)
void combine_kernel(float* __restrict__ out)
{
    const int h = blockIdx.z;
    const float* A = g_s + (size_t)h * N_E * N_E;   // [n][m]
    const float* B = g_d + (size_t)h * N_E * LR;    // [m][lr]

    __shared__ float As[16][132];
    __shared__ float Bs[16][132];

    const int tid = threadIdx.x;
    const int row0 = blockIdx.y * 128;   // n
    const int col0 = blockIdx.x * 128;   // lr (512 total -> gridDim.x = 4)
    const int tr = tid >> 4, tc = tid & 15;

    float acc[8][8];
#pragma unroll
    for (int i = 0; i < 8; i++)
#pragma unroll
        for (int j = 0; j < 8; j++) acc[i][j] = 0.f;

    for (int k0 = 0; k0 < N_E; k0 += 16) {
        // A: 128 rows x 16 k, transposed
#pragma unroll
        for (int i = 0; i < 2; i++) {
            int l = tid + i * 256;
            int r = l >> 2, c4 = (l & 3) << 2;
            float4 v = *(const float4*)(A + (size_t)(row0 + r) * N_E + k0 + c4);
            As[c4 + 0][r] = v.x; As[c4 + 1][r] = v.y;
            As[c4 + 2][r] = v.z; As[c4 + 3][r] = v.w;
        }
        // B: 16 k rows x 128 cols, natural
#pragma unroll
        for (int i = 0; i < 2; i++) {
            int l  = tid + i * 256;
            int kf = l >> 5, c4 = (l & 31) << 2;
            *(float4*)&Bs[kf][c4] = *(const float4*)(B + (size_t)(k0 + kf) * LR + col0 + c4);
        }
        __syncthreads();
#pragma unroll
        for (int k = 0; k < 16; k++) {
            float a[8], b[8];
            *(float4*)(a)     = *(const float4*)&As[k][tr * 4];
            *(float4*)(a + 4) = *(const float4*)&As[k][tr * 4 + 64];
            *(float4*)(b)     = *(const float4*)&Bs[k][tc * 4];
            *(float4*)(b + 4) = *(const float4*)&Bs[k][tc * 4 + 64];
#pragma unroll
            for (int i = 0; i < 8; i++)
#pragma unroll
                for (int j = 0; j < 8; j++) acc[i][j] += a[i] * b[j];
        }
        __syncthreads();
    }

#pragma unroll
    for (int i = 0; i < 8; i++) {
        int rn = row0 + tr * 4 + (i & 3) + ((i >> 2) << 6);
#pragma unroll
        for (int j = 0; j < 8; j += 4) {
            int c = col0 + tc * 4 + ((j >> 2) << 6);
            float4 v = make_float4(acc[i][j], acc[i][j + 1], acc[i][j + 2], acc[i][j + 3]);
            *(float4*)&out[(size_t)rn * HLR + h * LR + c] = v;
        }
    }
}

// ============================================================
extern "C" void kernel_launch(void* const* d_in, const int* in_sizes, int n_in,
                              void* d_out, int out_size)
{
    const float* x  = (const float*)d_in[0];
    const float* Wq = (const float*)d_in[1];
    const float* Wk = (const float*)d_in[2];
    const float* Wd = (const float*)d_in[3];
    float* out = (float*)d_out;

    proj_kernel<<<dim3(128, 4, 3), 256>>>(Wq, Wk, Wd, x);
    norm_kernel<<<dim3(N_E, 3), 256>>>();
    scores_kernel<<<dim3(16, 16, HEAD), 256>>>();
    softmax_kernel<<<HEAD * N_E, 256>>>();
    combine_kernel<<<dim3(4, 16, HEAD), 256>>>(out);
}

// round 7
// speedup vs baseline: 3.7744x; 2.3349x over previous
#include <cuda_runtime.h>
#include <cuda_bf16.h>
#include <math.h>
#include <stdint.h>

#define N_E   2048
#define HEAD  8
#define HLR   4096

// ---------------- fp32 scratch ----------------
__device__ float g_q[(size_t)HEAD * N_E * 512];
__device__ float g_k[(size_t)HEAD * N_E * 512];
__device__ float g_d[(size_t)HEAD * N_E * 512];
__device__ float g_s[(size_t)HEAD * N_E * N_E];
__device__ float g_inv[3 * N_E];

// ---------------- bf16 split operands ----------------
__device__ __nv_bfloat16 bx_hi[(size_t)16384 * 512];
__device__ __nv_bfloat16 bx_lo[(size_t)16384 * 512];
__device__ __nv_bfloat16 bw_hi[(size_t)1536 * 512];
__device__ __nv_bfloat16 bw_lo[(size_t)1536 * 512];
__device__ __nv_bfloat16 bq_hi[(size_t)HEAD * N_E * 512];
__device__ __nv_bfloat16 bq_lo[(size_t)HEAD * N_E * 512];
__device__ __nv_bfloat16 bk_hi[(size_t)HEAD * N_E * 512];
__device__ __nv_bfloat16 bk_lo[(size_t)HEAD * N_E * 512];
__device__ __nv_bfloat16 bs_hi[(size_t)HEAD * N_E * N_E];
__device__ __nv_bfloat16 bs_lo[(size_t)HEAD * N_E * N_E];
__device__ __nv_bfloat16 bdt_hi[(size_t)HEAD * 512 * N_E];
__device__ __nv_bfloat16 bdt_lo[(size_t)HEAD * 512 * N_E];

// ---------------- warp-MMA GEMM core ----------------
#define BM 128
#define BN 128
#define BK 64
#define STG 3
#define STAGE_BYTES (BM * 128 + BN * 128)      // 32768 (A then B, 128B rows)
#define SMEM_DYN (STG * STAGE_BYTES)           // 98304

__device__ __forceinline__ void cp16(uint32_t s, const void* g) {
    asm volatile("cp.async.cg.shared.global [%0], [%1], 16;\n"
                 :: "r"(s), "l"(__cvta_generic_to_global(g)));
}
__device__ __forceinline__ void cp_commit() { asm volatile("cp.async.commit_group;\n" ::: "memory"); }
__device__ __forceinline__ void cp_wait1()  { asm volatile("cp.async.wait_group 1;\n" ::: "memory"); }

__device__ __forceinline__ void ldsm4(uint32_t* r, uint32_t a) {
    asm volatile("ldmatrix.sync.aligned.m8n8.x4.shared.b16 {%0,%1,%2,%3}, [%4];"
                 : "=r"(r[0]), "=r"(r[1]), "=r"(r[2]), "=r"(r[3]) : "r"(a));
}
__device__ __forceinline__ void mma16816(float* c, const uint32_t* a, const uint32_t* b) {
    asm volatile("mma.sync.aligned.m16n8k16.row.col.f32.bf16.bf16.f32 "
                 "{%0,%1,%2,%3}, {%4,%5,%6,%7}, {%8,%9}, {%0,%1,%2,%3};"
                 : "+f"(c[0]), "+f"(c[1]), "+f"(c[2]), "+f"(c[3])
                 : "r"(a[0]), "r"(a[1]), "r"(a[2]), "r"(a[3]), "r"(b[0]), "r"(b[1]));
}

// one stage: A 128x64 bf16, B 128x64 bf16, 128B rows, unit-XOR swizzle
__device__ __forceinline__ void load_stage(uint32_t s,
                                           const __nv_bfloat16* __restrict__ A,
                                           const __nv_bfloat16* __restrict__ B, int ldk) {
    const int tid = threadIdx.x;
#pragma unroll
    for (int i = 0; i < 4; i++) {
        int idx = tid + i * 256, r = idx >> 3, c = idx & 7;
        cp16(s + r * 128 + ((c ^ (r & 7)) << 4), A + (size_t)r * ldk + c * 8);
    }
#pragma unroll
    for (int i = 0; i < 4; i++) {
        int idx = tid + i * 256, r = idx >> 3, c = idx & 7;
        cp16(s + BM * 128 + r * 128 + ((c ^ (r & 7)) << 4), B + (size_t)r * ldk + c * 8);
    }
    cp_commit();
}

// 3-pass hi/lo mainloop; acc[mf][j][0..3] = m16n8 frags, j = n8 index within warp's 32 cols
__device__ __forceinline__ void gemm_run(float (&acc)[4][4][4],
    const __nv_bfloat16* __restrict__ Ahi, const __nv_bfloat16* __restrict__ Alo,
    const __nv_bfloat16* __restrict__ Bhi, const __nv_bfloat16* __restrict__ Blo,
    const int ldk, const int KT)
{
    extern __shared__ char smem[];
    const uint32_t sb = (uint32_t)__cvta_generic_to_shared(smem);
    const int tid = threadIdx.x, lid = tid & 31, wid = tid >> 5;
    const int mw = wid >> 2, nw = wid & 3;
    const int TT = 3 * KT;

    const __nv_bfloat16* Ap[3] = {Ahi, Alo, Ahi};
    const __nv_bfloat16* Bp[3] = {Bhi, Bhi, Blo};

#pragma unroll
    for (int mf = 0; mf < 4; mf++)
#pragma unroll
        for (int j = 0; j < 4; j++)
#pragma unroll
            for (int e = 0; e < 4; e++) acc[mf][j][e] = 0.f;

    // per-lane ldmatrix rows
    int rowA[4], rowB[2];
#pragma unroll
    for (int mf = 0; mf < 4; mf++)
        rowA[mf] = mw * 64 + mf * 16 + ((lid >> 3) & 1) * 8 + (lid & 7);
#pragma unroll
    for (int nf = 0; nf < 2; nf++)
        rowB[nf] = nw * 32 + nf * 16 + (lid >> 4) * 8 + (lid & 7);
    const int uhA = lid >> 4;
    const int uB  = (lid >> 3) & 1;

    // prologue: tiles 0..STG-2
#pragma unroll
    for (int s = 0; s < STG - 1; s++)
        load_stage(sb + s * STAGE_BYTES, Ap[0] + (size_t)s * BK, Bp[0] + (size_t)s * BK, ldk);

    for (int t = 0; t < TT; t++) {
        cp_wait1();
        __syncthreads();
        int tn = t + STG - 1;
        if (tn < TT) {
            int p = tn / KT, kt = tn - p * KT;
            load_stage(sb + (tn % STG) * STAGE_BYTES,
                       Ap[p] + (size_t)kt * BK, Bp[p] + (size_t)kt * BK, ldk);
        } else {
            cp_commit();
        }
        const uint32_t sA = sb + (t % STG) * STAGE_BYTES;
        const uint32_t sB = sA + BM * 128;
#pragma unroll
        for (int ks = 0; ks < 4; ks++) {
            uint32_t a[4][4], b[2][4];
#pragma unroll
            for (int mf = 0; mf < 4; mf++)
                ldsm4(a[mf], sA + rowA[mf] * 128 + (((ks * 2 + uhA) ^ (rowA[mf] & 7)) << 4));
#pragma unroll
            for (int nf = 0; nf < 2; nf++)
                ldsm4(b[nf], sB + rowB[nf] * 128 + (((ks * 2 + uB) ^ (rowB[nf] & 7)) << 4));
#pragma unroll
            for (int mf = 0; mf < 4; mf++)
#pragma unroll
                for (int nf = 0; nf < 2; nf++) {
                    mma16816(acc[mf][nf * 2],     a[mf], &b[nf][0]);
                    mma16816(acc[mf][nf * 2 + 1], a[mf], &b[nf][2]);
                }
        }
    }
}

// ============================================================
// GEMM 1: proj  C[hq'(1536)][c(16384)] = Wcat . xr^T, scatter to g_q/g_k/g_d
// ============================================================
__global__ __launch_bounds__(256) void proj_gemm() {
    const int row0 = blockIdx.y * BM, col0 = blockIdx.x * BN;
    float acc[4][4][4];
    gemm_run(acc, bw_hi + (size_t)row0 * 512, bw_lo + (size_t)row0 * 512,
                  bx_hi + (size_t)col0 * 512, bx_lo + (size_t)col0 * 512, 512, 8);
    const int lid = threadIdx.x & 31, wid = threadIdx.x >> 5;
    const int mw = wid >> 2, nw = wid & 3;
#pragma unroll
    for (int mf = 0; mf < 4; mf++) {
        int row = row0 + mw * 64 + mf * 16 + (lid >> 2);
        float* OUT = (row < 512) ? g_q : (row < 1024) ? g_k : g_d;
        int h = (row >> 6) & 7, ql = row & 63;
        float* base = OUT + (size_t)h * N_E * 512;
#pragma unroll
        for (int j = 0; j < 4; j++) {
            int col = col0 + nw * 32 + j * 8 + ((lid & 3) << 1);
            int n = col >> 3, r = col & 7;
            *(float2*)&base[(size_t)n * 512 + ql * 8 + r]       = make_float2(acc[mf][j][0], acc[mf][j][1]);
            *(float2*)&base[(size_t)n * 512 + (ql + 8) * 8 + r] = make_float2(acc[mf][j][2], acc[mf][j][3]);
        }
    }
}

// ============================================================
// GEMM 2: scores  S[h][n][m] = bq . bk^T (fp32)
// ============================================================
__global__ __launch_bounds__(256) void scores_gemm() {
    const int h = blockIdx.z, row0 = blockIdx.y * BM, col0 = blockIdx.x * BN;
    const size_t ho = (size_t)h * N_E * 512;
    float acc[4][4][4];
    gemm_run(acc, bq_hi + ho + (size_t)row0 * 512, bq_lo + ho + (size_t)row0 * 512,
                  bk_hi + ho + (size_t)col0 * 512, bk_lo + ho + (size_t)col0 * 512, 512, 8);
    const int lid = threadIdx.x & 31, wid = threadIdx.x >> 5;
    const int mw = wid >> 2, nw = wid & 3;
    float* C = g_s + (size_t)h * N_E * N_E;
#pragma unroll
    for (int mf = 0; mf < 4; mf++) {
        int row = row0 + mw * 64 + mf * 16 + (lid >> 2);
#pragma unroll
        for (int j = 0; j < 4; j++) {
            int col = col0 + nw * 32 + j * 8 + ((lid & 3) << 1);
            *(float2*)&C[(size_t)row * N_E + col]       = make_float2(acc[mf][j][0], acc[mf][j][1]);
            *(float2*)&C[(size_t)(row + 8) * N_E + col] = make_float2(acc[mf][j][2], acc[mf][j][3]);
        }
    }
}

// ============================================================
// GEMM 3: combine  out[n][h*512+lr] = weights[h][n][:] . dT[h][lr][:]^T
// ============================================================
__global__ __launch_bounds__(256) void combine_gemm(float* __restrict__ out) {
    const int h = blockIdx.z, row0 = blockIdx.y * BM, col0 = blockIdx.x * BN;
    float acc[4][4][4];
    gemm_run(acc, bs_hi  + (size_t)h * N_E * N_E + (size_t)row0 * N_E,
                  bs_lo  + (size_t)h * N_E * N_E + (size_t)row0 * N_E,
                  bdt_hi + (size_t)h * 512 * N_E + (size_t)col0 * N_E,
                  bdt_lo + (size_t)h * 512 * N_E + (size_t)col0 * N_E, N_E, 32);
    const int lid = threadIdx.x & 31, wid = threadIdx.x >> 5;
    const int mw = wid >> 2, nw = wid & 3;
#pragma unroll
    for (int mf = 0; mf < 4; mf++) {
        int row = row0 + mw * 64 + mf * 16 + (lid >> 2);
#pragma unroll
        for (int j = 0; j < 4; j++) {
            int col = col0 + nw * 32 + j * 8 + ((lid & 3) << 1);
            *(float2*)&out[(size_t)row * HLR + h * 512 + col]       = make_float2(acc[mf][j][0], acc[mf][j][1]);
            *(float2*)&out[(size_t)(row + 8) * HLR + h * 512 + col] = make_float2(acc[mf][j][2], acc[mf][j][3]);
        }
    }
}

// ============================================================
// converts / norm / softmax
// ============================================================
__device__ __forceinline__ void split_bf16(float v, __nv_bfloat16& hi, __nv_bfloat16& lo) {
    hi = __float2bfloat16(v);
    lo = __float2bfloat16(v - __bfloat162float(hi));
}

__global__ void convert_w_kernel(const float* __restrict__ Wq, const float* __restrict__ Wk,
                                 const float* __restrict__ Wd) {
    int idx = (blockIdx.x * 256 + threadIdx.x) * 4;      // 1536*512 total
    int row = idx >> 9, col = idx & 511;
    const float* src = row < 512 ? Wq : row < 1024 ? Wk : Wd;
    float4 v = *(const float4*)&src[(size_t)(row & 511) * 512 + col];
    __nv_bfloat16 h0, h1, h2, h3, l0, l1, l2, l3;
    split_bf16(v.x, h0, l0); split_bf16(v.y, h1, l1);
    split_bf16(v.z, h2, l2); split_bf16(v.w, h3, l3);
    __nv_bfloat162* dh = (__nv_bfloat162*)&bw_hi[idx];
    __nv_bfloat162* dl = (__nv_bfloat162*)&bw_lo[idx];
    dh[0] = __halves2bfloat162(h0, h1); dh[1] = __halves2bfloat162(h2, h3);
    dl[0] = __halves2bfloat162(l0, l1); dl[1] = __halves2bfloat162(l2, l3);
}

// x[n][f][r] -> xr[n*8+r][f]
__global__ void convert_x_kernel(const float* __restrict__ x) {
    __shared__ float sx[4096];
    const float* xp = x + (size_t)blockIdx.x * 4096;
    for (int i = threadIdx.x; i < 1024; i += 256)
        ((float4*)sx)[i] = ((const float4*)xp)[i];
    __syncthreads();
    for (int i = threadIdx.x; i < 2048; i += 256) {
        int r = i >> 8, f = (i & 255) * 2;
        float a = sx[f * 8 + r], b = sx[f * 8 + 8 + r];
        __nv_bfloat16 ha, hb, la, lb;
        split_bf16(a, ha, la); split_bf16(b, hb, lb);
        size_t o = ((size_t)blockIdx.x * 8 + r) * 512 + f;
        *(__nv_bfloat162*)&bx_hi[o] = __halves2bfloat162(ha, hb);
        *(__nv_bfloat162*)&bx_lo[o] = __halves2bfloat162(la, lb);
    }
}

__global__ void norm_kernel() {
    const int which = blockIdx.y, n = blockIdx.x, tid = threadIdx.x;
    const float* P = (which == 0) ? g_q : (which == 1) ? g_k : g_d;
    float s = 0.f;
    for (int i = tid; i < 1024; i += 256) {
        int h = i >> 7, off = (i & 127) << 2;
        float4 v = *(const float4*)&P[(size_t)(h * N_E + n) * 512 + off];
        s += v.x * v.x + v.y * v.y + v.z * v.z + v.w * v.w;
    }
#pragma unroll
    for (int o = 16; o; o >>= 1) s += __shfl_xor_sync(0xffffffffu, s, o);
    __shared__ float ws[8];
    if ((tid & 31) == 0) ws[tid >> 5] = s;
    __syncthreads();
    if (tid == 0) {
        float t = 0.f;
#pragma unroll
        for (int w = 0; w < 8; w++) t += ws[w];
        g_inv[which * N_E + n] = rsqrtf(t);
    }
}

__global__ void convert_qk_kernel() {
    int hn = blockIdx.x, which = blockIdx.y;
    const float* src = which ? g_k : g_q;
    __nv_bfloat16* dh = which ? bk_hi : bq_hi;
    __nv_bfloat16* dl = which ? bk_lo : bq_lo;
    float inv = g_inv[which * N_E + (hn & (N_E - 1))];
    size_t base = (size_t)hn * 512 + threadIdx.x * 2;
    float2 v = *(const float2*)&src[base];
    __nv_bfloat16 ha, hb, la, lb;
    split_bf16(v.x * inv, ha, la); split_bf16(v.y * inv, hb, lb);
    *(__nv_bfloat162*)&dh[base] = __halves2bfloat162(ha, hb);
    *(__nv_bfloat162*)&dl[base] = __halves2bfloat162(la, lb);
}

// d[h][m][lr] -> dT[h][lr][m], inv_d folded
__global__ void convert_d_kernel() {
    __shared__ float tile[32][33];
    int h = blockIdx.z, j0 = blockIdx.x * 32, m0 = blockIdx.y * 32;
    int tx = threadIdx.x & 31, ty = threadIdx.x >> 5;
    const float* src = g_d + (size_t)h * N_E * 512;
#pragma unroll
    for (int i = 0; i < 4; i++) {
        int ml = ty + i * 8, m = m0 + ml;
        tile[ml][tx] = src[(size_t)m * 512 + j0 + tx] * g_inv[2 * N_E + m];
    }
    __syncthreads();
#pragma unroll
    for (int i = 0; i < 4; i++) {
        int jl = ty + i * 8;
        __nv_bfloat16 hi, lo; split_bf16(tile[tx][jl], hi, lo);
        size_t o = ((size_t)h * 512 + j0 + jl) * N_E + m0 + tx;
        bdt_hi[o] = hi; bdt_lo[o] = lo;
    }
}

__global__ void softmax_kernel() {
    const int row = blockIdx.x, tid = threadIdx.x;
    const float* S = g_s + (size_t)row * N_E;

    float4 v0 = *(const float4*)&S[tid * 4];
    float4 v1 = *(const float4*)&S[1024 + tid * 4];
    float mx = fmaxf(fmaxf(fmaxf(v0.x, v0.y), fmaxf(v0.z, v0.w)),
                     fmaxf(fmaxf(v1.x, v1.y), fmaxf(v1.z, v1.w)));
#pragma unroll
    for (int o = 16; o; o >>= 1) mx = fmaxf(mx, __shfl_xor_sync(0xffffffffu, mx, o));
    __shared__ float sm_max[8], sm_sum[8];
    if ((tid & 31) == 0) sm_max[tid >> 5] = mx;
    __syncthreads();
    mx = sm_max[0];
#pragma unroll
    for (int w = 1; w < 8; w++) mx = fmaxf(mx, sm_max[w]);

    float e[8];
    e[0] = expf(v0.x - mx); e[1] = expf(v0.y - mx); e[2] = expf(v0.z - mx); e[3] = expf(v0.w - mx);
    e[4] = expf(v1.x - mx); e[5] = expf(v1.y - mx); e[6] = expf(v1.z - mx); e[7] = expf(v1.w - mx);
    float s = e[0] + e[1] + e[2] + e[3] + e[4] + e[5] + e[6] + e[7];
#pragma unroll
    for (int o = 16; o; o >>= 1) s += __shfl_xor_sync(0xffffffffu, s, o);
    if ((tid & 31) == 0) sm_sum[tid >> 5] = s;
    __syncthreads();
    s = 0.f;
#pragma unroll
    for (int w = 0; w < 8; w++) s += sm_sum[w];
    float inv = 1.f / s;

    __nv_bfloat16 hi[8], lo[8];
#pragma unroll
    for (int i = 0; i < 8; i++) split_bf16(e[i] * inv, hi[i], lo[i]);

    size_t b0 = (size_t)row * N_E + tid * 4;
    size_t b1 = b0 + 1024;
    *(__nv_bfloat162*)&bs_hi[b0]     = __halves2bfloat162(hi[0], hi[1]);
    *(__nv_bfloat162*)&bs_hi[b0 + 2] = __halves2bfloat162(hi[2], hi[3]);
    *(__nv_bfloat162*)&bs_hi[b1]     = __halves2bfloat162(hi[4], hi[5]);
    *(__nv_bfloat162*)&bs_hi[b1 + 2] = __halves2bfloat162(hi[6], hi[7]);
    *(__nv_bfloat162*)&bs_lo[b0]     = __halves2bfloat162(lo[0], lo[1]);
    *(__nv_bfloat162*)&bs_lo[b0 + 2] = __halves2bfloat162(lo[2], lo[3]);
    *(__nv_bfloat162*)&bs_lo[b1]     = __halves2bfloat162(lo[4], lo[5]);
    *(__nv_bfloat162*)&bs_lo[b1 + 2] = __halves2bfloat162(lo[6], lo[7]);
}

// ============================================================
extern "C" void kernel_launch(void* const* d_in, const int* in_sizes, int n_in,
                              void* d_out, int out_size)
{
    const float* x  = (const float*)d_in[0];
    const float* Wq = (const float*)d_in[1];
    const float* Wk = (const float*)d_in[2];
    const float* Wd = (const float*)d_in[3];
    float* out = (float*)d_out;

    static int inited = 0;
    if (!inited) {
        cudaFuncSetAttribute(proj_gemm,    cudaFuncAttributeMaxDynamicSharedMemorySize, SMEM_DYN);
        cudaFuncSetAttribute(scores_gemm,  cudaFuncAttributeMaxDynamicSharedMemorySize, SMEM_DYN);
        cudaFuncSetAttribute(combine_gemm, cudaFuncAttributeMaxDynamicSharedMemorySize, SMEM_DYN);
        inited = 1;
    }

    convert_w_kernel<<<768, 256>>>(Wq, Wk, Wd);
    convert_x_kernel<<<N_E, 256>>>(x);
    proj_gemm<<<dim3(128, 12), 256, SMEM_DYN>>>();
    norm_kernel<<<dim3(N_E, 3), 256>>>();
    convert_qk_kernel<<<dim3(HEAD * N_E, 2), 256>>>();
    convert_d_kernel<<<dim3(16, 64, HEAD), 256>>>();
    scores_gemm<<<dim3(16, 16, HEAD), 256, SMEM_DYN>>>();
    softmax_kernel<<<HEAD * N_E, 256>>>();
    combine_gemm<<<dim3(4, 16, HEAD), 256, SMEM_DYN>>>(out);
}

// round 9
// speedup vs baseline: 3.8367x; 1.0165x over previous
#include <cuda_runtime.h>
#include <cuda_bf16.h>
#include <math.h>
#include <stdint.h>

#define N_E   2048
#define HEAD  8
#define HLR   4096

// ---------------- small fp32 scratch ----------------
__device__ float g_sumsq[3 * N_E];
__device__ float g_inv[3 * N_E];            // rsqrt norms (q,k,d)
__device__ float g_rowsum[HEAD * N_E];      // softmax denominators

// ---------------- bf16 split operands ----------------
__device__ __nv_bfloat16 bx_hi[(size_t)16384 * 512];        // xr[n*8+r][f]
__device__ __nv_bfloat16 bx_lo[(size_t)16384 * 512];
__device__ __nv_bfloat16 bw_hi[(size_t)1536 * 512];         // W concat [hq'][f]
__device__ __nv_bfloat16 bw_lo[(size_t)1536 * 512];
__device__ __nv_bfloat16 bq_hi[(size_t)HEAD * N_E * 512];   // unnormalized q [h][n][lr]
__device__ __nv_bfloat16 bq_lo[(size_t)HEAD * N_E * 512];
__device__ __nv_bfloat16 bk_hi[(size_t)HEAD * N_E * 512];
__device__ __nv_bfloat16 bk_lo[(size_t)HEAD * N_E * 512];
__device__ __nv_bfloat16 bd_hi[(size_t)HEAD * N_E * 512];   // unnormalized d [h][m][lr]
__device__ __nv_bfloat16 bd_lo[(size_t)HEAD * N_E * 512];
__device__ __nv_bfloat16 bs_hi[(size_t)HEAD * N_E * N_E];   // exp-weights [h][n][m]
__device__ __nv_bfloat16 bs_lo[(size_t)HEAD * N_E * N_E];
__device__ __nv_bfloat16 bdt_hi[(size_t)HEAD * 512 * N_E];  // dT [h][lr][m], inv_d folded
__device__ __nv_bfloat16 bdt_lo[(size_t)HEAD * 512 * N_E];

// ---------------- warp-MMA GEMM core: 128x256x64, 8 warps (2x4), warp tile 64x64 ----------------
#define BM 128
#define BN 256
#define BK 64
#define STG 3
#define STAGE_BYTES ((BM + BN) * 128)          // 49152
#define SMEM_DYN (STG * STAGE_BYTES)           // 147456

__device__ __forceinline__ void cp16(uint32_t s, const void* g) {
    asm volatile("cp.async.cg.shared.global [%0], [%1], 16;\n"
                 :: "r"(s), "l"(__cvta_generic_to_global(g)));
}
__device__ __forceinline__ void cp_commit() { asm volatile("cp.async.commit_group;\n" ::: "memory"); }
__device__ __forceinline__ void cp_wait1()  { asm volatile("cp.async.wait_group 1;\n" ::: "memory"); }

__device__ __forceinline__ void ldsm4(uint32_t* r, uint32_t a) {
    asm volatile("ldmatrix.sync.aligned.m8n8.x4.shared.b16 {%0,%1,%2,%3}, [%4];"
                 : "=r"(r[0]), "=r"(r[1]), "=r"(r[2]), "=r"(r[3]) : "r"(a));
}
__device__ __forceinline__ void mma16816(float* c, const uint32_t* a, const uint32_t* b) {
    asm volatile("mma.sync.aligned.m16n8k16.row.col.f32.bf16.bf16.f32 "
                 "{%0,%1,%2,%3}, {%4,%5,%6,%7}, {%8,%9}, {%0,%1,%2,%3};"
                 : "+f"(c[0]), "+f"(c[1]), "+f"(c[2]), "+f"(c[3])
                 : "r"(a[0]), "r"(a[1]), "r"(a[2]), "r"(a[3]), "r"(b[0]), "r"(b[1]));
}

// one stage: A 128x64 bf16 (16KB), B 256x64 bf16 (32KB), 128B rows, unit-XOR swizzle
__device__ __forceinline__ void load_stage(uint32_t s,
                                           const __nv_bfloat16* __restrict__ A,
                                           const __nv_bfloat16* __restrict__ B, int ldk) {
    const int tid = threadIdx.x;
#pragma unroll
    for (int i = 0; i < 4; i++) {
        int idx = tid + i * 256, r = idx >> 3, c = idx & 7;
        cp16(s + r * 128 + ((c ^ (r & 7)) << 4), A + (size_t)r * ldk + c * 8);
    }
#pragma unroll
    for (int i = 0; i < 8; i++) {
        int idx = tid + i * 256, r = idx >> 3, c = idx & 7;
        cp16(s + BM * 128 + r * 128 + ((c ^ (r & 7)) << 4), B + (size_t)r * ldk + c * 8);
    }
    cp_commit();
}

// 3-pass hi/lo mainloop; acc[mf][j][.] = m16n8 frags, j = n8 tile within warp's 64 cols
__device__ __forceinline__ void gemm_run(float (&acc)[4][8][4],
    const __nv_bfloat16* __restrict__ Ahi, const __nv_bfloat16* __restrict__ Alo,
    const __nv_bfloat16* __restrict__ Bhi, const __nv_bfloat16* __restrict__ Blo,
    const int ldk, const int KT)
{
    extern __shared__ char smem[];
    const uint32_t sb = (uint32_t)__cvta_generic_to_shared(smem);
    const int tid = threadIdx.x, lid = tid & 31, wid = tid >> 5;
    const int mw = wid >> 2, nw = wid & 3;
    const int TT = 3 * KT;

    const __nv_bfloat16* Ap[3] = {Ahi, Alo, Ahi};
    const __nv_bfloat16* Bp[3] = {Bhi, Bhi, Blo};

#pragma unroll
    for (int mf = 0; mf < 4; mf++)
#pragma unroll
        for (int j = 0; j < 8; j++)
#pragma unroll
            for (int e = 0; e < 4; e++) acc[mf][j][e] = 0.f;

    int rowA[4], rowB[4];
#pragma unroll
    for (int mf = 0; mf < 4; mf++)
        rowA[mf] = mw * 64 + mf * 16 + ((lid >> 3) & 1) * 8 + (lid & 7);
#pragma unroll
    for (int nf = 0; nf < 4; nf++)
        rowB[nf] = nw * 64 + nf * 16 + (lid >> 4) * 8 + (lid & 7);
    const int uhA = lid >> 4;
    const int uB  = (lid >> 3) & 1;

#pragma unroll
    for (int s = 0; s < STG - 1; s++)
        load_stage(sb + s * STAGE_BYTES, Ap[0] + (size_t)s * BK, Bp[0] + (size_t)s * BK, ldk);

    for (int t = 0; t < TT; t++) {
        cp_wait1();
        __syncthreads();
        int tn = t + STG - 1;
        if (tn < TT) {
            int p = tn / KT, kt = tn - p * KT;
            load_stage(sb + (tn % STG) * STAGE_BYTES,
                       Ap[p] + (size_t)kt * BK, Bp[p] + (size_t)kt * BK, ldk);
        } else {
            cp_commit();
        }
        const uint32_t sA = sb + (t % STG) * STAGE_BYTES;
        const uint32_t sB = sA + BM * 128;
#pragma unroll
        for (int ks = 0; ks < 4; ks++) {
            uint32_t a[4][4], b[4][4];
#pragma unroll
            for (int mf = 0; mf < 4; mf++)
                ldsm4(a[mf], sA + rowA[mf] * 128 + (((ks * 2 + uhA) ^ (rowA[mf] & 7)) << 4));
#pragma unroll
            for (int nf = 0; nf < 4; nf++)
                ldsm4(b[nf], sB + rowB[nf] * 128 + (((ks * 2 + uB) ^ (rowB[nf] & 7)) << 4));
#pragma unroll
            for (int mf = 0; mf < 4; mf++)
#pragma unroll
                for (int nf = 0; nf < 4; nf++) {
                    mma16816(acc[mf][nf * 2],     a[mf], &b[nf][0]);
                    mma16816(acc[mf][nf * 2 + 1], a[mf], &b[nf][2]);
                }
        }
    }
}

__device__ __forceinline__ void split_bf16(float v, __nv_bfloat16& hi, __nv_bfloat16& lo) {
    hi = __float2bfloat16(v);
    lo = __float2bfloat16(v - __bfloat162float(hi));
}

// ============================================================
// GEMM 1: proj  C[hq'(1536)][c(16384)] = Wcat . xr^T
// epilogue: bf16-split scatter to bq/bk/bd + per-n sumsq atomics
// ============================================================
__global__ __launch_bounds__(256) void proj_gemm() {
    const int row0 = blockIdx.y * BM, col0 = blockIdx.x * BN;
    float acc[4][8][4];
    gemm_run(acc, bw_hi + (size_t)row0 * 512, bw_lo + (size_t)row0 * 512,
                  bx_hi + (size_t)col0 * 512, bx_lo + (size_t)col0 * 512, 512, 8);
    const int lid = threadIdx.x & 31, wid = threadIdx.x >> 5;
    const int mw = wid >> 2, nw = wid & 3;
    const int which = row0 >> 9;                         // 0=q,1=k,2=d
    __nv_bfloat16* DH = (which == 0) ? bq_hi : (which == 1) ? bk_hi : bd_hi;
    __nv_bfloat16* DL = (which == 0) ? bq_lo : (which == 1) ? bk_lo : bd_lo;

    float psum[8];
#pragma unroll
    for (int j = 0; j < 8; j++) psum[j] = 0.f;

#pragma unroll
    for (int mf = 0; mf < 4; mf++) {
        int row = row0 + mw * 64 + mf * 16 + (lid >> 2);
        int hq = row & 511, h = hq >> 6, ql = hq & 63;
#pragma unroll
        for (int j = 0; j < 8; j++) {
            int col = col0 + nw * 64 + j * 8 + ((lid & 3) << 1);
            int n = col >> 3, r = col & 7;
            float v0 = acc[mf][j][0], v1 = acc[mf][j][1];
            float v2 = acc[mf][j][2], v3 = acc[mf][j][3];
            psum[j] += v0 * v0 + v1 * v1 + v2 * v2 + v3 * v3;
            size_t o0 = ((size_t)(h * N_E + n)) * 512 + ql * 8 + r;
            __nv_bfloat16 h0, h1, h2, h3, l0, l1, l2, l3;
            split_bf16(v0, h0, l0); split_bf16(v1, h1, l1);
            split_bf16(v2, h2, l2); split_bf16(v3, h3, l3);
            *(__nv_bfloat162*)&DH[o0]      = __halves2bfloat162(h0, h1);
            *(__nv_bfloat162*)&DL[o0]      = __halves2bfloat162(l0, l1);
            *(__nv_bfloat162*)&DH[o0 + 64] = __halves2bfloat162(h2, h3);   // row ql+8
            *(__nv_bfloat162*)&DL[o0 + 64] = __halves2bfloat162(l2, l3);
        }
    }
    // per-warp reduce (all lanes share the same 8 n values), then atomics
#pragma unroll
    for (int j = 0; j < 8; j++) {
#pragma unroll
        for (int o = 16; o; o >>= 1) psum[j] += __shfl_xor_sync(0xffffffffu, psum[j], o);
    }
    if (lid == 0) {
        int nb = (col0 >> 3) + nw * 8;
#pragma unroll
        for (int j = 0; j < 8; j++)
            atomicAdd(&g_sumsq[which * N_E + nb + j], psum[j]);
    }
}

// ============================================================
// GEMM 2: scores -> exp-weights.  logit = (q.k)*inv_q[n]*inv_k[m], |logit|<=1
// epilogue: w = exp(logit) -> bf16 split + row-sum atomics (no softmax kernel)
// ============================================================
__global__ __launch_bounds__(256) void scores_gemm() {
    const int h = blockIdx.z, row0 = blockIdx.y * BM, col0 = blockIdx.x * BN;
    const size_t ho = (size_t)h * N_E * 512;
    float acc[4][8][4];
    gemm_run(acc, bq_hi + ho + (size_t)row0 * 512, bq_lo + ho + (size_t)row0 * 512,
                  bk_hi + ho + (size_t)col0 * 512, bk_lo + ho + (size_t)col0 * 512, 512, 8);
    const int lid = threadIdx.x & 31, wid = threadIdx.x >> 5;
    const int mw = wid >> 2, nw = wid & 3;
    __nv_bfloat16* SH = bs_hi + (size_t)h * N_E * N_E;
    __nv_bfloat16* SL = bs_lo + (size_t)h * N_E * N_E;

    float prow[4][2];
#pragma unroll
    for (int mf = 0; mf < 4; mf++) { prow[mf][0] = 0.f; prow[mf][1] = 0.f; }

#pragma unroll
    for (int mf = 0; mf < 4; mf++) {
        int rA = row0 + mw * 64 + mf * 16 + (lid >> 2);
        float iq0 = g_inv[rA], iq1 = g_inv[rA + 8];
#pragma unroll
        for (int j = 0; j < 8; j++) {
            int col = col0 + nw * 64 + j * 8 + ((lid & 3) << 1);
            float ik0 = g_inv[N_E + col], ik1 = g_inv[N_E + col + 1];
            float e0 = __expf(acc[mf][j][0] * iq0 * ik0);
            float e1 = __expf(acc[mf][j][1] * iq0 * ik1);
            float e2 = __expf(acc[mf][j][2] * iq1 * ik0);
            float e3 = __expf(acc[mf][j][3] * iq1 * ik1);
            prow[mf][0] += e0 + e1;
            prow[mf][1] += e2 + e3;
            __nv_bfloat16 h0, h1, h2, h3, l0, l1, l2, l3;
            split_bf16(e0, h0, l0); split_bf16(e1, h1, l1);
            split_bf16(e2, h2, l2); split_bf16(e3, h3, l3);
            size_t o0 = (size_t)rA * N_E + col;
            *(__nv_bfloat162*)&SH[o0]              = __halves2bfloat162(h0, h1);
            *(__nv_bfloat162*)&SL[o0]              = __halves2bfloat162(l0, l1);
            *(__nv_bfloat162*)&SH[o0 + 8 * N_E]    = __halves2bfloat162(h2, h3);
            *(__nv_bfloat162*)&SL[o0 + 8 * N_E]    = __halves2bfloat162(l2, l3);
        }
    }
    // quad-reduce across lanes sharing the same row (lid&3 varies cols)
#pragma unroll
    for (int mf = 0; mf < 4; mf++) {
#pragma unroll
        for (int rh = 0; rh < 2; rh++) {
            float v = prow[mf][rh];
            v += __shfl_xor_sync(0xffffffffu, v, 1);
            v += __shfl_xor_sync(0xffffffffu, v, 2);
            if ((lid & 3) == 0) {
                int rA = row0 + mw * 64 + mf * 16 + (lid >> 2) + rh * 8;
                atomicAdd(&g_rowsum[h * N_E + rA], v);
            }
        }
    }
}

// ============================================================
// GEMM 3: combine  out[n][h*512+lr] = (1/rowsum[n]) * sum_m w[n][m] * dT[lr][m]
// ============================================================
__global__ __launch_bounds__(256) void combine_gemm(float* __restrict__ out) {
    const int h = blockIdx.z, row0 = blockIdx.y * BM, col0 = blockIdx.x * BN;
    float acc[4][8][4];
    gemm_run(acc, bs_hi  + (size_t)h * N_E * N_E + (size_t)row0 * N_E,
                  bs_lo  + (size_t)h * N_E * N_E + (size_t)row0 * N_E,
                  bdt_hi + (size_t)h * 512 * N_E + (size_t)col0 * N_E,
                  bdt_lo + (size_t)h * 512 * N_E + (size_t)col0 * N_E, N_E, 32);
    const int lid = threadIdx.x & 31, wid = threadIdx.x >> 5;
    const int mw = wid >> 2, nw = wid & 3;
#pragma unroll
    for (int mf = 0; mf < 4; mf++) {
        int row = row0 + mw * 64 + mf * 16 + (lid >> 2);
        float is0 = 1.f / g_rowsum[h * N_E + row];
        float is1 = 1.f / g_rowsum[h * N_E + row + 8];
#pragma unroll
        for (int j = 0; j < 8; j++) {
            int col = col0 + nw * 64 + j * 8 + ((lid & 3) << 1);
            *(float2*)&out[(size_t)row * HLR + h * 512 + col] =
                make_float2(acc[mf][j][0] * is0, acc[mf][j][1] * is0);
            *(float2*)&out[(size_t)(row + 8) * HLR + h * 512 + col] =
                make_float2(acc[mf][j][2] * is1, acc[mf][j][3] * is1);
        }
    }
}

// ============================================================
// converts / small kernels
// ============================================================
__global__ void zero_kernel() {
    int i = blockIdx.x * 256 + threadIdx.x;
    if (i < 3 * N_E) g_sumsq[i] = 0.f;
    if (i < HEAD * N_E) g_rowsum[i] = 0.f;
}

__global__ void rsqrt_kernel() {
    int i = blockIdx.x * 256 + threadIdx.x;
    if (i < 3 * N_E) g_inv[i] = rsqrtf(g_sumsq[i]);
}

__global__ void convert_w_kernel(const float* __restrict__ Wq, const float* __restrict__ Wk,
                                 const float* __restrict__ Wd) {
    int idx = (blockIdx.x * 256 + threadIdx.x) * 4;      // 1536*512 total
    int row = idx >> 9, col = idx & 511;
    const float* src = row < 512 ? Wq : row < 1024 ? Wk : Wd;
    float4 v = *(const float4*)&src[(size_t)(row & 511) * 512 + col];
    __nv_bfloat16 h0, h1, h2, h3, l0, l1, l2, l3;
    split_bf16(v.x, h0, l0); split_bf16(v.y, h1, l1);
    split_bf16(v.z, h2, l2); split_bf16(v.w, h3, l3);
    __nv_bfloat162* dh = (__nv_bfloat162*)&bw_hi[idx];
    __nv_bfloat162* dl = (__nv_bfloat162*)&bw_lo[idx];
    dh[0] = __halves2bfloat162(h0, h1); dh[1] = __halves2bfloat162(h2, h3);
    dl[0] = __halves2bfloat162(l0, l1); dl[1] = __halves2bfloat162(l2, l3);
}

// x[n][f][r] -> xr[n*8+r][f]
__global__ void convert_x_kernel(const float* __restrict__ x) {
    __shared__ float sx[4096];
    const float* xp = x + (size_t)blockIdx.x * 4096;
    for (int i = threadIdx.x; i < 1024; i += 256)
        ((float4*)sx)[i] = ((const float4*)xp)[i];
    __syncthreads();
    for (int i = threadIdx.x; i < 2048; i += 256) {
        int r = i >> 8, f = (i & 255) * 2;
        float a = sx[f * 8 + r], b = sx[f * 8 + 8 + r];
        __nv_bfloat16 ha, hb, la, lb;
        split_bf16(a, ha, la); split_bf16(b, hb, lb);
        size_t o = ((size_t)blockIdx.x * 8 + r) * 512 + f;
        *(__nv_bfloat162*)&bx_hi[o] = __halves2bfloat162(ha, hb);
        *(__nv_bfloat162*)&bx_lo[o] = __halves2bfloat162(la, lb);
    }
}

// bd[h][m][lr] -> bdt[h][lr][m] with inv_d[m] folded; 64x64 tiles
__global__ void convert_d_kernel() {
    __shared__ float tile[64][65];
    const int h = blockIdx.z, j0 = blockIdx.x * 64, m0 = blockIdx.y * 64;
    const int t = threadIdx.x;
    const __nv_bfloat16* SH = bd_hi + (size_t)h * N_E * 512;
    const __nv_bfloat16* SL = bd_lo + (size_t)h * N_E * 512;
#pragma unroll
    for (int i = 0; i < 8; i++) {
        int ml = (t >> 5) + i * 8, m = m0 + ml;
        float inv = g_inv[2 * N_E + m];
        __nv_bfloat162 vh = *(const __nv_bfloat162*)&SH[(size_t)m * 512 + j0 + (t & 31) * 2];
        __nv_bfloat162 vl = *(const __nv_bfloat162*)&SL[(size_t)m * 512 + j0 + (t & 31) * 2];
        tile[ml][(t & 31) * 2]     = (__bfloat162float(vh.x) + __bfloat162float(vl.x)) * inv;
        tile[ml][(t & 31) * 2 + 1] = (__bfloat162float(vh.y) + __bfloat162float(vl.y)) * inv;
    }
    __syncthreads();
#pragma unroll
    for (int i = 0; i < 8; i++) {
        int jl = (t >> 5) + i * 8;
        float v0 = tile[(t & 31) * 2][jl], v1 = tile[(t & 31) * 2 + 1][jl];
        __nv_bfloat16 h0, h1, l0, l1;
        split_bf16(v0, h0, l0); split_bf16(v1, h1, l1);
        size_t o = ((size_t)h * 512 + j0 + jl) * N_E + m0 + (t & 31) * 2;
        *(__nv_bfloat162*)&bdt_hi[o] = __halves2bfloat162(h0, h1);
        *(__nv_bfloat162*)&bdt_lo[o] = __halves2bfloat162(l0, l1);
    }
}

// ============================================================
extern "C" void kernel_launch(void* const* d_in, const int* in_sizes, int n_in,
                              void* d_out, int out_size)
{
    const float* x  = (const float*)d_in[0];
    const float* Wq = (const float*)d_in[1];
    const float* Wk = (const float*)d_in[2];
    const float* Wd = (const float*)d_in[3];
    float* out = (float*)d_out;

    cudaFuncSetAttribute(proj_gemm,    cudaFuncAttributeMaxDynamicSharedMemorySize, SMEM_DYN);
    cudaFuncSetAttribute(scores_gemm,  cudaFuncAttributeMaxDynamicSharedMemorySize, SMEM_DYN);
    cudaFuncSetAttribute(combine_gemm, cudaFuncAttributeMaxDynamicSharedMemorySize, SMEM_DYN);

    zero_kernel<<<64, 256>>>();
    convert_w_kernel<<<768, 256>>>(Wq, Wk, Wd);
    convert_x_kernel<<<N_E, 256>>>(x);
    proj_gemm<<<dim3(64, 12), 256, SMEM_DYN>>>();
    rsqrt_kernel<<<24, 256>>>();
    convert_d_kernel<<<dim3(8, 32, HEAD), 256>>>();
    scores_gemm<<<dim3(8, 16, HEAD), 256, SMEM_DYN>>>();
    combine_gemm<<<dim3(2, 16, HEAD), 256, SMEM_DYN>>>(out);
}